// round 4
// baseline (speedup 1.0000x reference)
#include <cuda_runtime.h>
#include <cstdint>

// AdaMoeLayer: out[t] = sum_e w[t,e]*(x[t] @ W_e + b_e),  T=32768, D=512, E=8.
// tf32 mma.sync, with per-expert scaled tf32 X precomputed (zero arithmetic in
// the GEMM hot loop: pure LDS -> HMMA). Single fp32 accumulator across experts.

#define D_DIM 512
#define E_DIM 8
#define T_TOK 32768
#define MAX_THRESHOLD 0.25f

// ---- static device scratch ----
__device__ float g_w[T_TOK * E_DIM];                       // gate weights, 1 MB
__device__ float g_Wt[(size_t)E_DIM * D_DIM * D_DIM];      // tf32 W, 8 MB
__device__ float g_Xs[(size_t)E_DIM * T_TOK * D_DIM];      // tf32 w*x, 512 MB

// ---------------------------------------------------------------------------
__device__ __forceinline__ uint32_t smem_u32(const void* p) {
    uint32_t a;
    asm("{ .reg .u64 t; cvta.to.shared.u64 t, %1; cvt.u32.u64 %0, t; }"
        : "=r"(a) : "l"(p));
    return a;
}
__device__ __forceinline__ void cp16(uint32_t dst, const void* src) {
    asm volatile("cp.async.cg.shared.global [%0], [%1], 16;\n"
                 :: "r"(dst), "l"(__cvta_generic_to_global(src)) : "memory");
}
__device__ __forceinline__ uint32_t cvt_tf32(float x) {
    uint32_t u;
    asm("cvt.rna.tf32.f32 %0, %1;" : "=r"(u) : "f"(x));
    return u;
}
__device__ __forceinline__ void mma_tf32(float* c, const uint32_t* a, const uint32_t* b) {
    asm volatile(
        "mma.sync.aligned.m16n8k8.row.col.f32.tf32.tf32.f32 "
        "{%0,%1,%2,%3}, {%4,%5,%6,%7}, {%8,%9}, {%0,%1,%2,%3};"
        : "+f"(c[0]), "+f"(c[1]), "+f"(c[2]), "+f"(c[3])
        : "r"(a[0]), "r"(a[1]), "r"(a[2]), "r"(a[3]), "r"(b[0]), "r"(b[1]));
}

// ---------------------------------------------------------------------------
// Kernel 1: gating + write per-expert scaled tf32 X copies. One warp/token.
// ---------------------------------------------------------------------------
__global__ __launch_bounds__(256) void gating_kernel(
    const float* __restrict__ x,
    const float* __restrict__ Wg, const float* __restrict__ bg,
    const float* __restrict__ Wt, const float* __restrict__ bt)
{
    __shared__ float sWg[E_DIM][D_DIM];
    __shared__ float sWt[D_DIM];
    const int tid = threadIdx.x;
    for (int i = tid; i < E_DIM * D_DIM; i += 256) {
        int e = i / D_DIM, d = i - e * D_DIM;
        sWg[e][d] = Wg[d * E_DIM + e];
    }
    for (int i = tid; i < D_DIM; i += 256) sWt[i] = Wt[i];
    __syncthreads();

    const int warp = tid >> 5, lane = tid & 31;
    const int t = blockIdx.x * 8 + warp;
    const float* xr = x + (size_t)t * D_DIM;

    float acc[9];
#pragma unroll
    for (int e = 0; e < 9; e++) acc[e] = 0.f;
#pragma unroll
    for (int i = 0; i < D_DIM / 32; i++) {
        int d = lane + 32 * i;
        float xv = xr[d];
#pragma unroll
        for (int e = 0; e < E_DIM; e++) acc[e] = fmaf(xv, sWg[e][d], acc[e]);
        acc[8] = fmaf(xv, sWt[d], acc[8]);
    }
#pragma unroll
    for (int off = 16; off > 0; off >>= 1)
#pragma unroll
        for (int e = 0; e < 9; e++) acc[e] += __shfl_xor_sync(0xffffffffu, acc[e], off);

    float logit[E_DIM];
#pragma unroll
    for (int e = 0; e < E_DIM; e++) logit[e] = acc[e] + bg[e];
    float m = logit[0];
#pragma unroll
    for (int e = 1; e < E_DIM; e++) m = fmaxf(m, logit[e]);
    float p[E_DIM], s = 0.f;
#pragma unroll
    for (int e = 0; e < E_DIM; e++) { p[e] = expf(logit[e] - m); s += p[e]; }
    float inv_s = 1.f / s;
    float thr = (1.f / (1.f + expf(-(acc[8] + bt[0])))) * MAX_THRESHOLD;

    float w[E_DIM], ws = 0.f;
#pragma unroll
    for (int e = 0; e < E_DIM; e++) {
        float a = p[e] * inv_s - thr;
        w[e] = (a >= 0.f) ? a : 0.f;
        ws += w[e];
    }
    if (ws == 0.f) ws = 1.f;
    float inv_ws = 1.f / ws;
    float wn[E_DIM];
#pragma unroll
    for (int e = 0; e < E_DIM; e++) wn[e] = w[e] * inv_ws;

    if (lane < E_DIM) {
        float v = 0.f;
#pragma unroll
        for (int e = 0; e < E_DIM; e++) if (lane == e) v = wn[e];
        g_w[t * E_DIM + lane] = v;
    }

    // scaled tf32 X copies, coalesced float4 stores
#pragma unroll 1
    for (int i = 0; i < 4; i++) {
        int d = i * 128 + lane * 4;
        float4 xv = *reinterpret_cast<const float4*>(xr + d);
#pragma unroll
        for (int e = 0; e < E_DIM; e++) {
            uint4 o;
            o.x = cvt_tf32(wn[e] * xv.x);
            o.y = cvt_tf32(wn[e] * xv.y);
            o.z = cvt_tf32(wn[e] * xv.z);
            o.w = cvt_tf32(wn[e] * xv.w);
            *reinterpret_cast<uint4*>(g_Xs + ((size_t)e * T_TOK + t) * D_DIM + d) = o;
        }
    }
}

// ---------------------------------------------------------------------------
// Kernel 2: pre-round W_exp to tf32 (stored as fp32 bits).
// ---------------------------------------------------------------------------
__global__ __launch_bounds__(256) void wprep_kernel(const float* __restrict__ W)
{
    size_t i = ((size_t)blockIdx.x * 256 + threadIdx.x) * 4;
    float4 v = *reinterpret_cast<const float4*>(W + i);
    uint4 o;
    o.x = cvt_tf32(v.x); o.y = cvt_tf32(v.y);
    o.z = cvt_tf32(v.z); o.w = cvt_tf32(v.w);
    *reinterpret_cast<uint4*>(g_Wt + i) = o;
}

// ---------------------------------------------------------------------------
// Kernel 3: main GEMM.  Grid (2 N-tiles, 256 M-tiles), 512 threads.
// CTA tile 128x256; 16 warps (4x4); warp tile 32x64 (2 m16 x 8 n8).
// Expert-outer: 256 stages of (expert, 16-wide K chunk); 4-stage cp.async ring.
// ---------------------------------------------------------------------------
#define XS_STRIDE 20                        // floats per X row (80 B)
#define BS_STRIDE 264                       // floats per B row (1056 B)
#define XS_WORDS (128 * XS_STRIDE)          // 2560
#define BS_WORDS (16 * BS_STRIDE)           // 4224
#define SW_OFF 0                            // gate weights [e][m]  (1024)
#define BB_OFF 1024                         // bias [e][n]          (2048)
#define XS_OFF 3072
#define BS_OFF (XS_OFF + 4 * XS_WORDS)      // 13312
#define SMEM_WORDS (BS_OFF + 4 * BS_WORDS)  // 30208
#define SMEM_BYTES (SMEM_WORDS * 4)         // 120832

__device__ __forceinline__ void issue_stage(
    int tid, uint32_t sm_base, int s, int t0, int n0)
{
    const int e = s >> 5, kt = s & 31, buf = s & 3;
    // X tile: 128 rows x 4 float4 chunks
    {
        int row = tid >> 2, ch = tid & 3;
        uint32_t dst = sm_base + (XS_OFF + buf * XS_WORDS + row * XS_STRIDE) * 4 + ch * 16;
        cp16(dst, g_Xs + ((size_t)e * T_TOK + t0 + row) * D_DIM + kt * 16 + ch * 4);
    }
    // B tile: 16 k-rows x 64 float4 chunks (2 per thread)
#pragma unroll
    for (int i = 0; i < 2; i++) {
        int id = tid + (i << 9);
        int row = id >> 6, ch = id & 63;
        uint32_t dst = sm_base + (BS_OFF + buf * BS_WORDS + row * BS_STRIDE) * 4 + ch * 16;
        cp16(dst, g_Wt + ((size_t)e * D_DIM + kt * 16 + row) * D_DIM + n0 + ch * 4);
    }
    asm volatile("cp.async.commit_group;\n" ::: "memory");
}

__global__ __launch_bounds__(512, 1) void moe_mma_kernel(
    const float* __restrict__ bexp,
    float* __restrict__ out)
{
    extern __shared__ float smem[];
    const uint32_t sm_base = smem_u32(smem);
    const int tid = threadIdx.x;
    const int lane = tid & 31, wid = tid >> 5;
    const int g = lane >> 2, t4 = lane & 3;
    const int wm = (wid >> 2) * 32, wn = (wid & 3) * 64;
    const int n0 = blockIdx.x * 256;
    const int t0 = blockIdx.y * 128;

    // stage gate weights [e][m] and bias [e][n]
    for (int i = tid; i < 128 * E_DIM; i += 512) {
        int m = i >> 3, e = i & 7;
        smem[SW_OFF + e * 128 + m] = g_w[(size_t)(t0 + m) * E_DIM + e];
    }
    for (int i = tid; i < E_DIM * 256; i += 512) {
        int e = i >> 8, c = i & 255;
        smem[BB_OFF + i] = bexp[e * D_DIM + n0 + c];
    }

    float acc[2][8][4];
#pragma unroll
    for (int mt = 0; mt < 2; mt++)
#pragma unroll
        for (int nt = 0; nt < 8; nt++)
#pragma unroll
            for (int j = 0; j < 4; j++) acc[mt][nt][j] = 0.f;

    issue_stage(tid, sm_base, 0, t0, n0);
    issue_stage(tid, sm_base, 1, t0, n0);
    issue_stage(tid, sm_base, 2, t0, n0);

#pragma unroll 1
    for (int s = 0; s < 256; ++s) {
        if (s < 254)       asm volatile("cp.async.wait_group 2;\n" ::: "memory");
        else if (s == 254) asm volatile("cp.async.wait_group 1;\n" ::: "memory");
        else               asm volatile("cp.async.wait_group 0;\n" ::: "memory");
        __syncthreads();

        const int buf = s & 3;
        const float* Xb = smem + XS_OFF + buf * XS_WORDS;
        const float* Bb = smem + BS_OFF + buf * BS_WORDS;

#pragma unroll
        for (int k8 = 0; k8 < 16; k8 += 8) {
            uint32_t a[2][4];
#pragma unroll
            for (int mt = 0; mt < 2; mt++) {
                int r = wm + mt * 16 + g;
                a[mt][0] = __float_as_uint(Xb[r * XS_STRIDE + k8 + t4]);
                a[mt][1] = __float_as_uint(Xb[(r + 8) * XS_STRIDE + k8 + t4]);
                a[mt][2] = __float_as_uint(Xb[r * XS_STRIDE + k8 + t4 + 4]);
                a[mt][3] = __float_as_uint(Xb[(r + 8) * XS_STRIDE + k8 + t4 + 4]);
            }
#pragma unroll
            for (int nt = 0; nt < 8; nt++) {
                int n = wn + nt * 8 + g;
                uint32_t b[2];
                b[0] = __float_as_uint(Bb[(k8 + t4) * BS_STRIDE + n]);
                b[1] = __float_as_uint(Bb[(k8 + t4 + 4) * BS_STRIDE + n]);
                mma_tf32(acc[0][nt], a[0], b);
                mma_tf32(acc[1][nt], a[1], b);
            }
        }

        if (s + 3 < 256) issue_stage(tid, sm_base, s + 3, t0, n0);
    }

    __syncthreads();

    // ---- epilogue: add sum_e w_te * b_e[n], write out ----
#pragma unroll
    for (int mt = 0; mt < 2; mt++) {
#pragma unroll
        for (int rr = 0; rr < 2; rr++) {
            int row = wm + mt * 16 + g + rr * 8;
            float wv[E_DIM];
#pragma unroll
            for (int e = 0; e < E_DIM; e++) wv[e] = smem[SW_OFF + e * 128 + row];
#pragma unroll
            for (int nt = 0; nt < 8; nt++) {
                int cl = wn + nt * 8 + 2 * t4;
                float b0 = 0.f, b1 = 0.f;
#pragma unroll
                for (int e = 0; e < E_DIM; e++) {
                    b0 = fmaf(wv[e], smem[BB_OFF + e * 256 + cl], b0);
                    b1 = fmaf(wv[e], smem[BB_OFF + e * 256 + cl + 1], b1);
                }
                float2 v;
                v.x = acc[mt][nt][rr * 2 + 0] + b0;
                v.y = acc[mt][nt][rr * 2 + 1] + b1;
                *reinterpret_cast<float2*>(out + (size_t)(t0 + row) * D_DIM + n0 + cl) = v;
            }
        }
    }
}

// ---------------------------------------------------------------------------
extern "C" void kernel_launch(void* const* d_in, const int* in_sizes, int n_in,
                              void* d_out, int out_size)
{
    const float* x    = (const float*)d_in[0];
    const float* Wg   = (const float*)d_in[1];
    const float* bg   = (const float*)d_in[2];
    const float* Wt   = (const float*)d_in[3];
    const float* bt   = (const float*)d_in[4];
    const float* Wexp = (const float*)d_in[5];
    const float* bexp = (const float*)d_in[6];
    float* out        = (float*)d_out;

    const int T = in_sizes[0] / D_DIM;          // 32768

    cudaFuncSetAttribute(moe_mma_kernel,
                         cudaFuncAttributeMaxDynamicSharedMemorySize, SMEM_BYTES);

    gating_kernel<<<T / 8, 256>>>(x, Wg, bg, Wt, bt);
    wprep_kernel<<<E_DIM * D_DIM * D_DIM / 4 / 256, 256>>>(Wexp);
    moe_mma_kernel<<<dim3(2, T / 128), 512, SMEM_BYTES>>>(bexp, out);
}

// round 5
// speedup vs baseline: 1.0793x; 1.0793x over previous
#include <cuda_runtime.h>
#include <cstdint>

// AdaMoeLayer: out[t] = sum_e w[t,e]*(x[t] @ W_e + b_e),  T=32768, D=512, E=8.
// tf32 mma.sync. Expert-outer GEMM with a PURE LDS->HMMA hot loop:
//   acc_e = X @ W_e   (X, W pre-rounded to tf32 once)
//   o    += w[t,e] * acc_e   (register epilogue per expert)
// Single output pass; bias folded as sum_e w_e*b_e at the end.

#define D_DIM 512
#define E_DIM 8
#define T_TOK 32768
#define MAX_THRESHOLD 0.25f

// ---- static device scratch ----
__device__ float g_w[T_TOK * E_DIM];                      // gate weights, 1 MB
__device__ float g_Wt[(size_t)E_DIM * D_DIM * D_DIM];     // tf32 W, 8 MB
__device__ float g_Xt[(size_t)T_TOK * D_DIM];             // tf32 X, 64 MB

// ---------------------------------------------------------------------------
__device__ __forceinline__ uint32_t smem_u32(const void* p) {
    uint32_t a;
    asm("{ .reg .u64 t; cvta.to.shared.u64 t, %1; cvt.u32.u64 %0, t; }"
        : "=r"(a) : "l"(p));
    return a;
}
__device__ __forceinline__ void cp16(uint32_t dst, const void* src) {
    asm volatile("cp.async.cg.shared.global [%0], [%1], 16;\n"
                 :: "r"(dst), "l"(__cvta_generic_to_global(src)) : "memory");
}
__device__ __forceinline__ uint32_t cvt_tf32(float x) {
    uint32_t u;
    asm("cvt.rna.tf32.f32 %0, %1;" : "=r"(u) : "f"(x));
    return u;
}
__device__ __forceinline__ void mma_tf32(float* c, const uint32_t* a, const uint32_t* b) {
    asm volatile(
        "mma.sync.aligned.m16n8k8.row.col.f32.tf32.tf32.f32 "
        "{%0,%1,%2,%3}, {%4,%5,%6,%7}, {%8,%9}, {%0,%1,%2,%3};"
        : "+f"(c[0]), "+f"(c[1]), "+f"(c[2]), "+f"(c[3])
        : "r"(a[0]), "r"(a[1]), "r"(a[2]), "r"(a[3]), "r"(b[0]), "r"(b[1]));
}

// ---------------------------------------------------------------------------
// Kernel 1: gating only. One warp per token.
// ---------------------------------------------------------------------------
__global__ __launch_bounds__(256) void gating_kernel(
    const float* __restrict__ x,
    const float* __restrict__ Wg, const float* __restrict__ bg,
    const float* __restrict__ Wt, const float* __restrict__ bt)
{
    __shared__ float sWg[E_DIM][D_DIM];
    __shared__ float sWt[D_DIM];
    const int tid = threadIdx.x;
    for (int i = tid; i < E_DIM * D_DIM; i += 256) {
        int e = i / D_DIM, d = i - e * D_DIM;
        sWg[e][d] = Wg[d * E_DIM + e];
    }
    for (int i = tid; i < D_DIM; i += 256) sWt[i] = Wt[i];
    __syncthreads();

    const int warp = tid >> 5, lane = tid & 31;
    const int t = blockIdx.x * 8 + warp;
    const float* xr = x + (size_t)t * D_DIM;

    float acc[9];
#pragma unroll
    for (int e = 0; e < 9; e++) acc[e] = 0.f;
#pragma unroll
    for (int i = 0; i < D_DIM / 32; i++) {
        int d = lane + 32 * i;
        float xv = xr[d];
#pragma unroll
        for (int e = 0; e < E_DIM; e++) acc[e] = fmaf(xv, sWg[e][d], acc[e]);
        acc[8] = fmaf(xv, sWt[d], acc[8]);
    }
#pragma unroll
    for (int off = 16; off > 0; off >>= 1)
#pragma unroll
        for (int e = 0; e < 9; e++) acc[e] += __shfl_xor_sync(0xffffffffu, acc[e], off);

    float logit[E_DIM];
#pragma unroll
    for (int e = 0; e < E_DIM; e++) logit[e] = acc[e] + bg[e];
    float m = logit[0];
#pragma unroll
    for (int e = 1; e < E_DIM; e++) m = fmaxf(m, logit[e]);
    float p[E_DIM], s = 0.f;
#pragma unroll
    for (int e = 0; e < E_DIM; e++) { p[e] = expf(logit[e] - m); s += p[e]; }
    float inv_s = 1.f / s;
    float thr = (1.f / (1.f + expf(-(acc[8] + bt[0])))) * MAX_THRESHOLD;

    float w[E_DIM], ws = 0.f;
#pragma unroll
    for (int e = 0; e < E_DIM; e++) {
        float a = p[e] * inv_s - thr;
        w[e] = (a >= 0.f) ? a : 0.f;
        ws += w[e];
    }
    if (ws == 0.f) ws = 1.f;
    float inv_ws = 1.f / ws;

    if (lane < E_DIM) {
        float v = 0.f;
#pragma unroll
        for (int e = 0; e < E_DIM; e++) if (lane == e) v = w[e];
        g_w[t * E_DIM + lane] = v * inv_ws;
    }
}

// ---------------------------------------------------------------------------
// Kernel 2a/2b: pre-round W and X to tf32 (stored as fp32 bits).
// ---------------------------------------------------------------------------
__global__ __launch_bounds__(256) void wprep_kernel(const float* __restrict__ W)
{
    size_t i = ((size_t)blockIdx.x * 256 + threadIdx.x) * 4;
    float4 v = *reinterpret_cast<const float4*>(W + i);
    uint4 o;
    o.x = cvt_tf32(v.x); o.y = cvt_tf32(v.y);
    o.z = cvt_tf32(v.z); o.w = cvt_tf32(v.w);
    *reinterpret_cast<uint4*>(g_Wt + i) = o;
}
__global__ __launch_bounds__(256) void xprep_kernel(const float* __restrict__ X)
{
    size_t i = ((size_t)blockIdx.x * 256 + threadIdx.x) * 4;
    float4 v = *reinterpret_cast<const float4*>(X + i);
    uint4 o;
    o.x = cvt_tf32(v.x); o.y = cvt_tf32(v.y);
    o.z = cvt_tf32(v.z); o.w = cvt_tf32(v.w);
    *reinterpret_cast<uint4*>(g_Xt + i) = o;
}

// ---------------------------------------------------------------------------
// Kernel 3: main GEMM.  Grid (4 N-tiles, 256 M-tiles), 512 threads.
// CTA tile 128x128; 16 warps (4x4); warp tile 32x32.
// Stages: 8 experts x 16 K-chunks of 32 = 128 stages; 4-deep cp.async ring.
// Pure LDS->MMA in the hot loop; per-expert w fold in registers.
// ---------------------------------------------------------------------------
#define XS_STRIDE 36                        // floats per X row (144 B, bank-clean)
#define BS_STRIDE 136                       // floats per B row (544 B, bank-clean)
#define XS_WORDS (128 * XS_STRIDE)          // 4608
#define BS_WORDS (32 * BS_STRIDE)           // 4352
#define SW_OFF 0                            // gate weights [e][m]  (1024 floats)
#define BB_OFF 1024                         // bias [e][n]          (1024 floats)
#define XS_OFF 2048
#define BS_OFF (XS_OFF + 4 * XS_WORDS)      // 20480
#define SMEM_WORDS (BS_OFF + 4 * BS_WORDS)  // 37888
#define SMEM_BYTES (SMEM_WORDS * 4)         // 151552

__device__ __forceinline__ void issue_stage(
    int tid, uint32_t sm_base, int s, int t0, int n0)
{
    const int e = s >> 4, kt = s & 15, buf = s & 3;
    // X chunk: 128 rows x 8 float4  (1024 float4s, 2 per thread)
#pragma unroll
    for (int i = 0; i < 2; i++) {
        int id = tid + (i << 9);
        int row = id >> 3, ch = id & 7;
        uint32_t dst = sm_base + (XS_OFF + buf * XS_WORDS + row * XS_STRIDE + ch * 4) * 4;
        cp16(dst, g_Xt + (size_t)(t0 + row) * D_DIM + kt * 32 + ch * 4);
    }
    // B chunk: 32 k-rows x 32 float4  (1024 float4s, 2 per thread)
#pragma unroll
    for (int i = 0; i < 2; i++) {
        int id = tid + (i << 9);
        int row = id >> 5, ch = id & 31;
        uint32_t dst = sm_base + (BS_OFF + buf * BS_WORDS + row * BS_STRIDE + ch * 4) * 4;
        cp16(dst, g_Wt + ((size_t)e * D_DIM + kt * 32 + row) * D_DIM + n0 + ch * 4);
    }
    asm volatile("cp.async.commit_group;\n" ::: "memory");
}

__global__ __launch_bounds__(512, 1) void moe_mma_kernel(
    const float* __restrict__ bexp,
    float* __restrict__ out)
{
    extern __shared__ float smem[];
    const uint32_t sm_base = smem_u32(smem);
    const int tid = threadIdx.x;
    const int lane = tid & 31, wid = tid >> 5;
    const int g = lane >> 2, t4 = lane & 3;
    const int wm = (wid >> 2) * 32, wn = (wid & 3) * 32;
    const int n0 = blockIdx.x * 128;
    const int t0 = blockIdx.y * 128;

    // stage gate weights [e][m] and bias [e][n]
    for (int i = tid; i < 128 * E_DIM; i += 512) {
        int m = i >> 3, e = i & 7;
        smem[SW_OFF + e * 128 + m] = g_w[(size_t)(t0 + m) * E_DIM + e];
    }
    for (int i = tid; i < E_DIM * 128; i += 512) {
        int e = i >> 7, c = i & 127;
        smem[BB_OFF + i] = bexp[e * D_DIM + n0 + c];
    }

    float acc[2][4][4], o[2][4][4];
#pragma unroll
    for (int mt = 0; mt < 2; mt++)
#pragma unroll
        for (int nt = 0; nt < 4; nt++)
#pragma unroll
            for (int j = 0; j < 4; j++) { acc[mt][nt][j] = 0.f; o[mt][nt][j] = 0.f; }

    issue_stage(tid, sm_base, 0, t0, n0);
    issue_stage(tid, sm_base, 1, t0, n0);
    issue_stage(tid, sm_base, 2, t0, n0);

#pragma unroll 1
    for (int s = 0; s < 128; ++s) {
        if (s < 126)       asm volatile("cp.async.wait_group 2;\n" ::: "memory");
        else if (s == 126) asm volatile("cp.async.wait_group 1;\n" ::: "memory");
        else               asm volatile("cp.async.wait_group 0;\n" ::: "memory");
        __syncthreads();

        const int buf = s & 3;
        const float* Xb = smem + XS_OFF + buf * XS_WORDS;
        const float* Bb = smem + BS_OFF + buf * BS_WORDS;

#pragma unroll
        for (int k8 = 0; k8 < 32; k8 += 8) {
            uint32_t a[2][4];
#pragma unroll
            for (int mt = 0; mt < 2; mt++) {
                int r = wm + mt * 16 + g;
                a[mt][0] = __float_as_uint(Xb[r * XS_STRIDE + k8 + t4]);
                a[mt][1] = __float_as_uint(Xb[(r + 8) * XS_STRIDE + k8 + t4]);
                a[mt][2] = __float_as_uint(Xb[r * XS_STRIDE + k8 + t4 + 4]);
                a[mt][3] = __float_as_uint(Xb[(r + 8) * XS_STRIDE + k8 + t4 + 4]);
            }
#pragma unroll
            for (int nt = 0; nt < 4; nt++) {
                int n = wn + nt * 8 + g;
                uint32_t b[2];
                b[0] = __float_as_uint(Bb[(k8 + t4) * BS_STRIDE + n]);
                b[1] = __float_as_uint(Bb[(k8 + t4 + 4) * BS_STRIDE + n]);
                mma_tf32(acc[0][nt], a[0], b);
                mma_tf32(acc[1][nt], a[1], b);
            }
        }

        if (s + 3 < 128) issue_stage(tid, sm_base, s + 3, t0, n0);

        // expert boundary: fold acc into o with gate weight, reset acc
        if ((s & 15) == 15) {
            const int e = s >> 4;
#pragma unroll
            for (int mt = 0; mt < 2; mt++) {
#pragma unroll
                for (int rr = 0; rr < 2; rr++) {
                    float wv = smem[SW_OFF + e * 128 + wm + mt * 16 + g + rr * 8];
#pragma unroll
                    for (int nt = 0; nt < 4; nt++) {
#pragma unroll
                        for (int j = 0; j < 2; j++) {
                            o[mt][nt][rr * 2 + j] =
                                fmaf(wv, acc[mt][nt][rr * 2 + j], o[mt][nt][rr * 2 + j]);
                            acc[mt][nt][rr * 2 + j] = 0.f;
                        }
                    }
                }
            }
        }
    }

    __syncthreads();

    // ---- epilogue: add sum_e w_te * b_e[n], write out ----
#pragma unroll
    for (int mt = 0; mt < 2; mt++) {
#pragma unroll
        for (int rr = 0; rr < 2; rr++) {
            int row = wm + mt * 16 + g + rr * 8;
            float wv[E_DIM];
#pragma unroll
            for (int e = 0; e < E_DIM; e++) wv[e] = smem[SW_OFF + e * 128 + row];
#pragma unroll
            for (int nt = 0; nt < 4; nt++) {
                int cl = wn + nt * 8 + 2 * t4;
                float b0 = 0.f, b1 = 0.f;
#pragma unroll
                for (int e = 0; e < E_DIM; e++) {
                    b0 = fmaf(wv[e], smem[BB_OFF + e * 128 + cl], b0);
                    b1 = fmaf(wv[e], smem[BB_OFF + e * 128 + cl + 1], b1);
                }
                float2 v;
                v.x = o[mt][nt][rr * 2 + 0] + b0;
                v.y = o[mt][nt][rr * 2 + 1] + b1;
                *reinterpret_cast<float2*>(out + (size_t)(t0 + row) * D_DIM + n0 + cl) = v;
            }
        }
    }
}

// ---------------------------------------------------------------------------
extern "C" void kernel_launch(void* const* d_in, const int* in_sizes, int n_in,
                              void* d_out, int out_size)
{
    const float* x    = (const float*)d_in[0];
    const float* Wg   = (const float*)d_in[1];
    const float* bg   = (const float*)d_in[2];
    const float* Wt   = (const float*)d_in[3];
    const float* bt   = (const float*)d_in[4];
    const float* Wexp = (const float*)d_in[5];
    const float* bexp = (const float*)d_in[6];
    float* out        = (float*)d_out;

    const int T = in_sizes[0] / D_DIM;          // 32768

    cudaFuncSetAttribute(moe_mma_kernel,
                         cudaFuncAttributeMaxDynamicSharedMemorySize, SMEM_BYTES);

    gating_kernel<<<T / 8, 256>>>(x, Wg, bg, Wt, bt);
    xprep_kernel<<<T * D_DIM / 4 / 256, 256>>>(x);
    wprep_kernel<<<E_DIM * D_DIM * D_DIM / 4 / 256, 256>>>(Wexp);
    moe_mma_kernel<<<dim3(4, T / 128), 512, SMEM_BYTES>>>(bexp, out);
}